// round 8
// baseline (speedup 1.0000x reference)
#include <cuda_runtime.h>
#include <cuda_fp16.h>
#include <cuda_fp8.h>
#include <cstdint>

// ---------------------------------------------------------------------------
// Problem constants (fixed shapes: x,y = [4096,1024] fp32, scalar output)
// ---------------------------------------------------------------------------
#define BROWS 4096
#define DDIM  1024
#define EPSF  1e-6f

// Quantization pre-scale: 16*component in e4m3 AND f16; acc = 256*S.
// exp(S/tau) = exp2(acc * log2(e) / (0.07 * 256))
#define QSCALE 16.0f
#define K2LOG_S (20.6099287984152302f / 256.0f)

// Hybrid split: tensor pipe (fp8 mma.sync, ~324 MAC/cyc/SM) does k in [0,768);
// fma pipe (HFMA2, 128 MAC/cyc/SM, rt2 measured) does k in [768,1024).
#define KTEN 6                   // tensor chunks of 128
#define BM 128
#define BN 128
#define BK 128
#define STAGES 3
// fp8 stage: A,B 128x128B each, XOR-swizzled (no pad)
#define STAGE_BYTES (2 * BM * 128)               // 32768
#define AH_OFF  (STAGES * STAGE_BYTES)           // 98304; Ah: 128 rows x 512B
#define BH_OFF  (AH_OFF + BM * 512)              // 163840; Bh: 128 cols x 528B
#define SMEM_BYTES (BH_OFF + BN * 528)           // 231424 (<= 232448 opt-in)

// ---------------------------------------------------------------------------
// Scratch (device globals: allocation-free rule)
// ---------------------------------------------------------------------------
__device__ uint8_t g_xq[(size_t)BROWS * DDIM];   // e4m3 (k<768 used)
__device__ uint8_t g_yq[(size_t)BROWS * DDIM];
__device__ __half2 g_xh[(size_t)BROWS * 128];    // f16, k in [768,1024), scaled 16
__device__ __half2 g_yh[(size_t)BROWS * 128];
__device__ float g_rowsum[BROWS];
__device__ float g_colsum[BROWS];
__device__ float g_diag[BROWS];

// scalar k-unit (8k) schedule across the 6 tensor iterations: 32 units total
__constant__ int UST[6] = {0, 6, 11, 16, 22, 27};
__constant__ int UEN[6] = {6, 11, 16, 22, 27, 32};

// ---------------------------------------------------------------------------
// PTX helpers (<= sm_89; nothing 'a'-gated)
// ---------------------------------------------------------------------------
static __device__ __forceinline__ uint32_t smem_u32(const void* p) {
    uint32_t a;
    asm("{ .reg .u64 t; cvta.to.shared.u64 t, %1; cvt.u32.u64 %0, t; }"
        : "=r"(a) : "l"(p));
    return a;
}
static __device__ __forceinline__ float ex2f(float x) {
    float y;
    asm("ex2.approx.ftz.f32 %0, %1;" : "=f"(y) : "f"(x));
    return y;
}
static __device__ __forceinline__ void cp16(uint32_t dst, const void* src) {
    asm volatile("cp.async.cg.shared.global [%0], [%1], 16;"
                 :: "r"(dst), "l"(src) : "memory");
}
#define CP_COMMIT() asm volatile("cp.async.commit_group;" ::: "memory")
#define CP_WAIT(n)  asm volatile("cp.async.wait_group %0;" :: "n"(n) : "memory")

static __device__ __forceinline__ void ldmatrix_x4(
    uint32_t& r0, uint32_t& r1, uint32_t& r2, uint32_t& r3, uint32_t addr) {
    asm volatile("ldmatrix.sync.aligned.m8n8.x4.shared.b16 {%0,%1,%2,%3}, [%4];"
                 : "=r"(r0), "=r"(r1), "=r"(r2), "=r"(r3) : "r"(addr));
}
static __device__ __forceinline__ void mma16832(
    float* d, const uint32_t* a, const uint32_t* b) {
    asm volatile(
        "mma.sync.aligned.m16n8k32.row.col.f32.e4m3.e4m3.f32 "
        "{%0,%1,%2,%3}, {%4,%5,%6,%7}, {%8,%9}, {%0,%1,%2,%3};"
        : "+f"(d[0]), "+f"(d[1]), "+f"(d[2]), "+f"(d[3])
        : "r"(a[0]), "r"(a[1]), "r"(a[2]), "r"(a[3]), "r"(b[0]), "r"(b[1]));
}
static __device__ __forceinline__ uint32_t pack_fp8x4(
    float a, float b, float c, float d) {
    const __nv_fp8x2_storage_t lo =
        __nv_cvt_float2_to_fp8x2(make_float2(a, b), __NV_SATFINITE, __NV_E4M3);
    const __nv_fp8x2_storage_t hi =
        __nv_cvt_float2_to_fp8x2(make_float2(c, d), __NV_SATFINITE, __NV_E4M3);
    return (uint32_t)lo | ((uint32_t)hi << 16);
}

// ---------------------------------------------------------------------------
// Kernel 1: normalize -> fp8 (all k) + f16 (k>=768), fp32 diag, zeroing
//   128 threads/row (R7 shape, measured 9.8us)
// ---------------------------------------------------------------------------
__global__ void __launch_bounds__(128) norm_kernel(
    const float* __restrict__ x, const float* __restrict__ y) {
    const int i = blockIdx.x;
    const int tid = threadIdx.x;
    const int wid = tid >> 5, lane = tid & 31;

    const float4* xr = reinterpret_cast<const float4*>(x) + (size_t)i * 256;
    const float4* yr = reinterpret_cast<const float4*>(y) + (size_t)i * 256;
    const float4 x0 = xr[tid], x1 = xr[tid + 128];
    const float4 y0 = yr[tid], y1 = yr[tid + 128];

    float ssx = x0.x * x0.x + x0.y * x0.y + x0.z * x0.z + x0.w * x0.w
              + x1.x * x1.x + x1.y * x1.y + x1.z * x1.z + x1.w * x1.w;
    float ssy = y0.x * y0.x + y0.y * y0.y + y0.z * y0.z + y0.w * y0.w
              + y1.x * y1.x + y1.y * y1.y + y1.z * y1.z + y1.w * y1.w;
    float sxy = x0.x * y0.x + x0.y * y0.y + x0.z * y0.z + x0.w * y0.w
              + x1.x * y1.x + x1.y * y1.y + x1.z * y1.z + x1.w * y1.w;
#pragma unroll
    for (int m = 16; m; m >>= 1) {
        ssx += __shfl_xor_sync(0xffffffffu, ssx, m);
        ssy += __shfl_xor_sync(0xffffffffu, ssy, m);
        sxy += __shfl_xor_sync(0xffffffffu, sxy, m);
    }
    __shared__ float s0[4], s1[4], s2[4];
    if (lane == 0) { s0[wid] = ssx; s1[wid] = ssy; s2[wid] = sxy; }
    __syncthreads();
    const float a = s0[0] + s0[1] + s0[2] + s0[3];
    const float b = s1[0] + s1[1] + s1[2] + s1[3];
    const float c = s2[0] + s2[1] + s2[2] + s2[3];
    const float invx = 1.0f / fmaxf(sqrtf(a), EPSF);
    const float invy = 1.0f / fmaxf(sqrtf(b), EPSF);
    if (tid == 0) {
        g_diag[i] = c * invx * invy;
        g_rowsum[i] = 0.f;
        g_colsum[i] = 0.f;
    }
    const float qx = QSCALE * invx, qy = QSCALE * invy;
    uint32_t* ox = reinterpret_cast<uint32_t*>(g_xq + (size_t)i * DDIM);
    uint32_t* oy = reinterpret_cast<uint32_t*>(g_yq + (size_t)i * DDIM);
    ox[tid]       = pack_fp8x4(x0.x * qx, x0.y * qx, x0.z * qx, x0.w * qx);
    ox[tid + 128] = pack_fp8x4(x1.x * qx, x1.y * qx, x1.z * qx, x1.w * qx);
    oy[tid]       = pack_fp8x4(y0.x * qy, y0.y * qy, y0.z * qy, y0.w * qy);
    oy[tid + 128] = pack_fp8x4(y1.x * qy, y1.y * qy, y1.z * qy, y1.w * qy);

    // f16 copies of k in [768,1024): x1/y1 cover k = 4*tid+512 -> tid >= 64
    if (tid >= 64) {
        const int o = (tid - 64) * 2;    // half2 index within 128-wide row
        __half2* hx = g_xh + (size_t)i * 128 + o;
        __half2* hy = g_yh + (size_t)i * 128 + o;
        hx[0] = __floats2half2_rn(x1.x * qx, x1.y * qx);
        hx[1] = __floats2half2_rn(x1.z * qx, x1.w * qx);
        hy[0] = __floats2half2_rn(y1.x * qy, y1.y * qy);
        hy[1] = __floats2half2_rn(y1.z * qy, y1.w * qy);
    }
}

// ---------------------------------------------------------------------------
// Kernel 2: hybrid tensor+fma GEMM tile + fused exp / row+col sums
//   grid (32,32); 512 threads; warp grid 4x4; MMA warp tile 32x32 (k<768);
//   scalar: warp w rows 8w..8w+7, lane c cols {c,c+32,c+64,c+96} (k>=768)
// ---------------------------------------------------------------------------
static __device__ __forceinline__ void load_stage(
    uint32_t sbase, int p, const uint8_t* gA, const uint8_t* gB, int tid) {
    const int s = p % STAGES;
    const uint32_t aBase = sbase + (uint32_t)(s * STAGE_BYTES);
    const uint32_t bBase = aBase + (uint32_t)(BM * 128);
    // A/B: 128 rows x 8 chunks(16B), XOR swizzle chunk^=(row&7); 2 per thread
#pragma unroll
    for (int r = 0; r < 2; ++r) {
        const int idx = tid + r * 512;
        const int row = idx >> 3, ch = idx & 7;
        const uint32_t off = (uint32_t)(row * 128 + ((ch ^ (row & 7)) << 4));
        cp16(aBase + off, gA + (size_t)(p * BK) + (size_t)row * DDIM + ch * 16);
        cp16(bBase + off, gB + (size_t)(p * BK) + (size_t)row * DDIM + ch * 16);
    }
    CP_COMMIT();
}

__global__ void __launch_bounds__(512, 1) gemm_exp_kernel() {
    extern __shared__ uint8_t smem[];
    const uint32_t sbase = smem_u32(smem);
    const int tid = threadIdx.x;
    const int lane = tid & 31;
    const int wid = tid >> 5;
    const int warp_m = wid & 3;
    const int warp_n = wid >> 2;
    const int i_base = blockIdx.x * BM;
    const int j_base = blockIdx.y * BN;
    const uint8_t* gA = g_xq + (size_t)i_base * DDIM;
    const uint8_t* gB = g_yq + (size_t)j_base * DDIM;

    float acc[2][4][4];
#pragma unroll
    for (int mi = 0; mi < 2; ++mi)
#pragma unroll
        for (int ni = 0; ni < 4; ++ni)
#pragma unroll
            for (int r = 0; r < 4; ++r) acc[mi][ni][r] = 0.f;

    __half2 sacc[8][4];
#pragma unroll
    for (int i = 0; i < 8; ++i)
#pragma unroll
        for (int g = 0; g < 4; ++g) sacc[i][g] = __floats2half2_rn(0.f, 0.f);

    // ---- prologue: stage0 fp8 + ALL f16 halves in group G0; stage1 in G1 ----
    {
        const int s = 0;
        const uint32_t aBase = sbase + (uint32_t)(s * STAGE_BYTES);
        const uint32_t bBase = aBase + (uint32_t)(BM * 128);
#pragma unroll
        for (int r = 0; r < 2; ++r) {
            const int idx = tid + r * 512;
            const int row = idx >> 3, ch = idx & 7;
            const uint32_t off = (uint32_t)(row * 128 + ((ch ^ (row & 7)) << 4));
            cp16(aBase + off, gA + (size_t)row * DDIM + ch * 16);
            cp16(bBase + off, gB + (size_t)row * DDIM + ch * 16);
        }
        // Ah: 128 rows x 512B (32 chunks/row), 8 per thread
#pragma unroll
        for (int r = 0; r < 8; ++r) {
            const int idx = tid + r * 512;
            const int row = idx >> 5, ch = idx & 31;
            cp16(sbase + AH_OFF + (uint32_t)(row * 512 + ch * 16),
                 (const uint8_t*)(g_xh + (size_t)(i_base + row) * 128) + ch * 16);
        }
        // Bh: 128 cols x 512B data (row stride 528), 8 per thread
#pragma unroll
        for (int r = 0; r < 8; ++r) {
            const int idx = tid + r * 512;
            const int row = idx >> 5, ch = idx & 31;
            cp16(sbase + BH_OFF + (uint32_t)(row * 528 + ch * 16),
                 (const uint8_t*)(g_yh + (size_t)(j_base + row) * 128) + ch * 16);
        }
        CP_COMMIT();
    }
    load_stage(sbase, 1, gA, gB, tid);

    const uint32_t lrow = (uint32_t)(lane & 15);
    const uint32_t khalf = (uint32_t)(lane >> 4);   // 0/1 -> +16B within k32

    for (int kt = 0; kt < KTEN; ++kt) {
        CP_WAIT(1);
        __syncthreads();
        if (kt + STAGES - 1 < KTEN)
            load_stage(sbase, kt + STAGES - 1, gA, gB, tid);

        const int s = kt % STAGES;
        const uint32_t aTile = sbase + (uint32_t)(s * STAGE_BYTES);
        const uint32_t bTile = aTile + (uint32_t)(BM * 128);

#pragma unroll
        for (int kk = 0; kk < 4; ++kk) {
            uint32_t a[2][4];
#pragma unroll
            for (int mi = 0; mi < 2; ++mi) {
                const uint32_t row = (uint32_t)(warp_m * 32 + mi * 16) + lrow;
                const uint32_t ch = (uint32_t)(kk * 2) + khalf;
                ldmatrix_x4(a[mi][0], a[mi][1], a[mi][2], a[mi][3],
                            aTile + row * 128 + ((ch ^ (row & 7)) << 4));
            }
            uint32_t b[4][2];
#pragma unroll
            for (int p = 0; p < 2; ++p) {
                const uint32_t row = (uint32_t)(warp_n * 32 + p * 16) + lrow;
                const uint32_t ch = (uint32_t)(kk * 2) + khalf;
                uint32_t r0, r1, r2, r3;
                ldmatrix_x4(r0, r1, r2, r3,
                            bTile + row * 128 + ((ch ^ (row & 7)) << 4));
                b[2 * p][0] = r0; b[2 * p + 1][0] = r1;
                b[2 * p][1] = r2; b[2 * p + 1][1] = r3;
            }
#pragma unroll
            for (int mi = 0; mi < 2; ++mi)
#pragma unroll
                for (int ni = 0; ni < 4; ++ni)
                    mma16832(acc[mi][ni], a[mi], b[ni]);
        }

        // ---- interleaved scalar slice on the fma pipe (k in [768,1024)) ----
        for (int u = UST[kt]; u < UEN[kt]; ++u) {
            const uint32_t ko = (uint32_t)(u * 16);
            uint4 bv[4];
#pragma unroll
            for (int g = 0; g < 4; ++g)
                bv[g] = *reinterpret_cast<const uint4*>(
                    smem + BH_OFF + (uint32_t)((lane + 32 * g) * 528) + ko);
#pragma unroll
            for (int i = 0; i < 8; ++i) {
                const uint4 av = *reinterpret_cast<const uint4*>(
                    smem + AH_OFF + (uint32_t)((wid * 8 + i) * 512) + ko);
                const __half2* ah = reinterpret_cast<const __half2*>(&av);
#pragma unroll
                for (int g = 0; g < 4; ++g) {
                    const __half2* bh = reinterpret_cast<const __half2*>(&bv[g]);
                    sacc[i][g] = __hfma2(ah[0], bh[0], sacc[i][g]);
                    sacc[i][g] = __hfma2(ah[1], bh[1], sacc[i][g]);
                    sacc[i][g] = __hfma2(ah[2], bh[2], sacc[i][g]);
                    sacc[i][g] = __hfma2(ah[3], bh[3], sacc[i][g]);
                }
            }
        }
    }
    __syncthreads();

    // ---- combine: scalar partials -> smem (float [128][128] at offset 0) ----
    float* sc = reinterpret_cast<float*>(smem);
#pragma unroll
    for (int i = 0; i < 8; ++i)
#pragma unroll
        for (int g = 0; g < 4; ++g) {
            const float2 p = __half22float2(sacc[i][g]);
            sc[(wid * 8 + i) * 128 + (lane + 32 * g)] = p.x + p.y;
        }
    __syncthreads();

    // ---------------- fused epilogue: exp + row/col sums ----------------
    const int m0 = i_base + warp_m * 32;
    const int n0 = j_base + warp_n * 32;
    const int gid = lane >> 2, tig = lane & 3;
    const int rl0 = warp_m * 32, cl0 = warp_n * 32;

    float rs[2][2] = {{0.f, 0.f}, {0.f, 0.f}};
    float cs[4][2];
#pragma unroll
    for (int ni = 0; ni < 4; ++ni) { cs[ni][0] = 0.f; cs[ni][1] = 0.f; }

#pragma unroll
    for (int mi = 0; mi < 2; ++mi)
#pragma unroll
        for (int ni = 0; ni < 4; ++ni) {
            const int r0 = rl0 + mi * 16 + gid;
            const int cc = cl0 + ni * 8 + 2 * tig;
            const float e0 = ex2f((acc[mi][ni][0] + sc[r0 * 128 + cc])       * K2LOG_S);
            const float e1 = ex2f((acc[mi][ni][1] + sc[r0 * 128 + cc + 1])   * K2LOG_S);
            const float e2 = ex2f((acc[mi][ni][2] + sc[(r0 + 8) * 128 + cc])     * K2LOG_S);
            const float e3 = ex2f((acc[mi][ni][3] + sc[(r0 + 8) * 128 + cc + 1]) * K2LOG_S);
            rs[mi][0] += e0 + e1;
            rs[mi][1] += e2 + e3;
            cs[ni][0] += e0 + e2;
            cs[ni][1] += e1 + e3;
        }

#pragma unroll
    for (int mi = 0; mi < 2; ++mi)
#pragma unroll
        for (int h = 0; h < 2; ++h) {
            float v = rs[mi][h];
            v += __shfl_xor_sync(0xffffffffu, v, 1);
            v += __shfl_xor_sync(0xffffffffu, v, 2);
            if (tig == 0)
                atomicAdd(&g_rowsum[m0 + mi * 16 + h * 8 + gid], v);
        }
#pragma unroll
    for (int ni = 0; ni < 4; ++ni)
#pragma unroll
        for (int h = 0; h < 2; ++h) {
            float v = cs[ni][h];
            v += __shfl_xor_sync(0xffffffffu, v, 4);
            v += __shfl_xor_sync(0xffffffffu, v, 8);
            v += __shfl_xor_sync(0xffffffffu, v, 16);
            if (gid == 0)
                atomicAdd(&g_colsum[n0 + ni * 8 + 2 * tig + h], v);
        }
}

// ---------------------------------------------------------------------------
// Kernel 3: final log-reduce -> scalar loss
// ---------------------------------------------------------------------------
__global__ void __launch_bounds__(256) finalize_kernel(float* __restrict__ out) {
    const int tid = threadIdx.x;
    const double extra = (double)BROWS * 1e-6 + 1e-6;
    double acc = 0.0;
    for (int i = tid; i < BROWS; i += 256) {
        const double t = 2.0 * (double)g_diag[i] / 0.07;
        acc += t - log((double)g_rowsum[i] + extra) - log((double)g_colsum[i] + extra);
    }
    __shared__ double sb[256];
    sb[tid] = acc;
    __syncthreads();
#pragma unroll
    for (int s = 128; s; s >>= 1) {
        if (tid < s) sb[tid] += sb[tid + s];
        __syncthreads();
    }
    if (tid == 0) out[0] = (float)(sb[0] * (-1.0 / (2.0 * (double)BROWS)));
}

// ---------------------------------------------------------------------------
extern "C" void kernel_launch(void* const* d_in, const int* in_sizes, int n_in,
                              void* d_out, int out_size) {
    const float* x = (const float*)d_in[0];
    const float* y = (const float*)d_in[1];
    float* out = (float*)d_out;

    static int configured = 0;
    if (!configured) {
        cudaFuncSetAttribute(gemm_exp_kernel,
                             cudaFuncAttributeMaxDynamicSharedMemorySize, SMEM_BYTES);
        configured = 1;
    }

    norm_kernel<<<BROWS, 128>>>(x, y);
    gemm_exp_kernel<<<dim3(BROWS / BM, BROWS / BN), 512, SMEM_BYTES>>>();
    finalize_kernel<<<1, 256>>>(out);
}

// round 9
// speedup vs baseline: 1.0295x; 1.0295x over previous
#include <cuda_runtime.h>
#include <cuda_fp16.h>
#include <cuda_fp8.h>
#include <cstdint>

// ---------------------------------------------------------------------------
// Problem constants (fixed shapes: x,y = [4096,1024] fp32, scalar output)
// ---------------------------------------------------------------------------
#define BROWS 4096
#define DDIM  1024
#define EPSF  1e-6f

// Quantization pre-scale: 16*component (e4m3 for k<768, f16 for k>=768);
// acc = 256*S. exp(S/tau) = exp2(acc * log2(e) / (0.07*256))
#define QSCALE 16.0f
#define K2LOG_S (20.6099287984152302f / 256.0f)

// Hybrid k-split with WARP SPECIALIZATION (R8 failed because scalar+MMA in
// the same warp serialize at QMMA issue; different warps overlap pipes):
//   warps 0-15: fp8 mma.sync, k in [0,768), R7-proven inner loop
//   warps 16-23: HFMA2 on the fma pipe, k in [768,1024)
#define KTEN 6                   // tensor chunks of 128
#define BM 128
#define BN 128
#define BK 128
#define STAGES 2
#define RS (BK + 16)             // fp8 smem row stride (R7 layout)
#define STAGE_BYTES ((BM + BN) * RS)             // 36864
#define AH_OFF (STAGES * STAGE_BYTES)            // 73728; Ah: 128 rows x 512B
#define BK_OFF (AH_OFF + BM * 512)               // 139264; Bk: 256 k x 272B
#define SMEM_BYTES (BK_OFF + 256 * 272)          // 208896 (<= 232448 opt-in)

// ---------------------------------------------------------------------------
// Scratch (device globals: allocation-free rule)
// ---------------------------------------------------------------------------
__device__ uint8_t g_xq[(size_t)BROWS * DDIM];   // e4m3 (k<768 used)
__device__ uint8_t g_yq[(size_t)BROWS * DDIM];
__device__ __half g_xh[(size_t)BROWS * 256];     // x f16, k in [768,1024), row-major
__device__ __half g_yhT[(size_t)256 * BROWS];    // y f16, k-major [k-768][row]
__device__ float g_rowsum[BROWS];
__device__ float g_colsum[BROWS];
__device__ float g_diag[BROWS];

// ---------------------------------------------------------------------------
// PTX helpers (<= sm_89; nothing 'a'-gated)
// ---------------------------------------------------------------------------
static __device__ __forceinline__ uint32_t smem_u32(const void* p) {
    uint32_t a;
    asm("{ .reg .u64 t; cvta.to.shared.u64 t, %1; cvt.u32.u64 %0, t; }"
        : "=r"(a) : "l"(p));
    return a;
}
static __device__ __forceinline__ float ex2f(float x) {
    float y;
    asm("ex2.approx.ftz.f32 %0, %1;" : "=f"(y) : "f"(x));
    return y;
}
static __device__ __forceinline__ void cp16(uint32_t dst, const void* src) {
    asm volatile("cp.async.cg.shared.global [%0], [%1], 16;"
                 :: "r"(dst), "l"(src) : "memory");
}
#define CP_COMMIT() asm volatile("cp.async.commit_group;" ::: "memory")
#define CP_WAIT(n)  asm volatile("cp.async.wait_group %0;" :: "n"(n) : "memory")
#define BAR_MMA()   asm volatile("bar.sync 1, 512;" ::: "memory")

static __device__ __forceinline__ void ldmatrix_x4(
    uint32_t& r0, uint32_t& r1, uint32_t& r2, uint32_t& r3, uint32_t addr) {
    asm volatile("ldmatrix.sync.aligned.m8n8.x4.shared.b16 {%0,%1,%2,%3}, [%4];"
                 : "=r"(r0), "=r"(r1), "=r"(r2), "=r"(r3) : "r"(addr));
}
static __device__ __forceinline__ void mma16832(
    float* d, const uint32_t* a, const uint32_t* b) {
    asm volatile(
        "mma.sync.aligned.m16n8k32.row.col.f32.e4m3.e4m3.f32 "
        "{%0,%1,%2,%3}, {%4,%5,%6,%7}, {%8,%9}, {%0,%1,%2,%3};"
        : "+f"(d[0]), "+f"(d[1]), "+f"(d[2]), "+f"(d[3])
        : "r"(a[0]), "r"(a[1]), "r"(a[2]), "r"(a[3]), "r"(b[0]), "r"(b[1]));
}
static __device__ __forceinline__ uint32_t pack_fp8x4(
    float a, float b, float c, float d) {
    const __nv_fp8x2_storage_t lo =
        __nv_cvt_float2_to_fp8x2(make_float2(a, b), __NV_SATFINITE, __NV_E4M3);
    const __nv_fp8x2_storage_t hi =
        __nv_cvt_float2_to_fp8x2(make_float2(c, d), __NV_SATFINITE, __NV_E4M3);
    return (uint32_t)lo | ((uint32_t)hi << 16);
}
static __device__ __forceinline__ uint32_t hfma2_acc(
    uint32_t acc, uint32_t a, uint32_t b) {
    asm("fma.rn.f16x2 %0, %1, %2, %0;" : "+r"(acc) : "r"(a), "r"(b));
    return acc;
}

// ---------------------------------------------------------------------------
// Kernel 1: normalize -> fp8 (all k) + f16 halves (k>=768; y transposed)
// ---------------------------------------------------------------------------
__global__ void __launch_bounds__(128) norm_kernel(
    const float* __restrict__ x, const float* __restrict__ y) {
    const int i = blockIdx.x;
    const int tid = threadIdx.x;
    const int wid = tid >> 5, lane = tid & 31;

    const float4* xr = reinterpret_cast<const float4*>(x) + (size_t)i * 256;
    const float4* yr = reinterpret_cast<const float4*>(y) + (size_t)i * 256;
    const float4 x0 = xr[tid], x1 = xr[tid + 128];
    const float4 y0 = yr[tid], y1 = yr[tid + 128];

    float ssx = x0.x * x0.x + x0.y * x0.y + x0.z * x0.z + x0.w * x0.w
              + x1.x * x1.x + x1.y * x1.y + x1.z * x1.z + x1.w * x1.w;
    float ssy = y0.x * y0.x + y0.y * y0.y + y0.z * y0.z + y0.w * y0.w
              + y1.x * y1.x + y1.y * y1.y + y1.z * y1.z + y1.w * y1.w;
    float sxy = x0.x * y0.x + x0.y * y0.y + x0.z * y0.z + x0.w * y0.w
              + x1.x * y1.x + x1.y * y1.y + x1.z * y1.z + x1.w * y1.w;
#pragma unroll
    for (int m = 16; m; m >>= 1) {
        ssx += __shfl_xor_sync(0xffffffffu, ssx, m);
        ssy += __shfl_xor_sync(0xffffffffu, ssy, m);
        sxy += __shfl_xor_sync(0xffffffffu, sxy, m);
    }
    __shared__ float s0[4], s1[4], s2[4];
    if (lane == 0) { s0[wid] = ssx; s1[wid] = ssy; s2[wid] = sxy; }
    __syncthreads();
    const float a = s0[0] + s0[1] + s0[2] + s0[3];
    const float b = s1[0] + s1[1] + s1[2] + s1[3];
    const float c = s2[0] + s2[1] + s2[2] + s2[3];
    const float invx = 1.0f / fmaxf(sqrtf(a), EPSF);
    const float invy = 1.0f / fmaxf(sqrtf(b), EPSF);
    if (tid == 0) {
        g_diag[i] = c * invx * invy;
        g_rowsum[i] = 0.f;
        g_colsum[i] = 0.f;
    }
    const float qx = QSCALE * invx, qy = QSCALE * invy;
    uint32_t* ox = reinterpret_cast<uint32_t*>(g_xq + (size_t)i * DDIM);
    uint32_t* oy = reinterpret_cast<uint32_t*>(g_yq + (size_t)i * DDIM);
    ox[tid]       = pack_fp8x4(x0.x * qx, x0.y * qx, x0.z * qx, x0.w * qx);
    ox[tid + 128] = pack_fp8x4(x1.x * qx, x1.y * qx, x1.z * qx, x1.w * qx);
    oy[tid]       = pack_fp8x4(y0.x * qy, y0.y * qy, y0.z * qy, y0.w * qy);
    oy[tid + 128] = pack_fp8x4(y1.x * qy, y1.y * qy, y1.z * qy, y1.w * qy);

    // f16 halves: x1/y1 cover k = 512+4*tid; k>=768 <=> tid>=64
    if (tid >= 64) {
        const int kk = 4 * tid - 256;   // 0..252
        __half2* hx = reinterpret_cast<__half2*>(g_xh + (size_t)i * 256 + kk);
        hx[0] = __floats2half2_rn(x1.x * qx, x1.y * qx);
        hx[1] = __floats2half2_rn(x1.z * qx, x1.w * qx);
        g_yhT[(size_t)(kk + 0) * BROWS + i] = __float2half_rn(y1.x * qy);
        g_yhT[(size_t)(kk + 1) * BROWS + i] = __float2half_rn(y1.y * qy);
        g_yhT[(size_t)(kk + 2) * BROWS + i] = __float2half_rn(y1.z * qy);
        g_yhT[(size_t)(kk + 3) * BROWS + i] = __float2half_rn(y1.w * qy);
    }
}

// ---------------------------------------------------------------------------
// Kernel 2: warp-specialized hybrid GEMM tile + fused exp / row+col sums
//   grid (32,32); 768 threads = 16 MMA warps + 8 FMA warps
// ---------------------------------------------------------------------------
static __device__ __forceinline__ void load_stage(
    uint32_t sbase, int p, const uint8_t* gA, const uint8_t* gB, int tid) {
    const int s = p % STAGES;
    const uint32_t aBase = sbase + (uint32_t)(s * STAGE_BYTES);
    const uint32_t bBase = aBase + (uint32_t)(BM * RS);
#pragma unroll
    for (int r = 0; r < 2; ++r) {
        const int idx = tid + r * 512;
        const int row = idx >> 3, c = idx & 7;
        cp16(aBase + (uint32_t)(row * RS + c * 16),
             gA + (size_t)(p * BK) + (size_t)row * DDIM + c * 16);
        cp16(bBase + (uint32_t)(row * RS + c * 16),
             gB + (size_t)(p * BK) + (size_t)row * DDIM + c * 16);
    }
    CP_COMMIT();
}

__global__ void __launch_bounds__(768, 1) gemm_exp_kernel() {
    extern __shared__ uint8_t smem[];
    const uint32_t sbase = smem_u32(smem);
    const int tid = threadIdx.x;
    const int lane = tid & 31;
    const int wid = tid >> 5;
    const int i_base = blockIdx.x * BM;
    const int j_base = blockIdx.y * BN;
    const uint8_t* gA = g_xq + (size_t)i_base * DDIM;
    const uint8_t* gB = g_yq + (size_t)j_base * DDIM;

    // ---------------- prologue loads ----------------
    if (wid < 16) {
        load_stage(sbase, 0, gA, gB, tid);     // stage 0 only; loop prefetches
    } else {
        const int ft = tid - 512;              // 0..255
        // Ah: 128 rows x 32 chunks (512B rows) from g_xh
#pragma unroll
        for (int r = 0; r < 16; ++r) {
            const int idx = ft + r * 256;
            const int row = idx >> 5, ch = idx & 31;
            cp16(sbase + AH_OFF + (uint32_t)(row * 512 + ch * 16),
                 g_xh + (size_t)(i_base + row) * 256 + ch * 8);
        }
        // Bk: 256 k-rows x 16 chunks (272B stride) from g_yhT
#pragma unroll
        for (int r = 0; r < 16; ++r) {
            const int idx = ft + r * 256;
            const int k = idx >> 4, ch = idx & 15;
            cp16(sbase + BK_OFF + (uint32_t)(k * 272 + ch * 16),
                 g_yhT + (size_t)k * BROWS + j_base + ch * 8);
        }
        CP_COMMIT();
    }
    CP_WAIT(0);
    __syncthreads();

    float acc[2][4][4];
    uint32_t sacc[16][2];   // FMA warps: half2 col-pair accumulators

    if (wid < 16) {
        // ================= MMA warps: k in [0,768) =================
        const int warp_m = wid & 3;
        const int warp_n = wid >> 2;
#pragma unroll
        for (int mi = 0; mi < 2; ++mi)
#pragma unroll
            for (int ni = 0; ni < 4; ++ni)
#pragma unroll
                for (int r = 0; r < 4; ++r) acc[mi][ni][r] = 0.f;

        const uint32_t lrow = (uint32_t)(lane & 15);
        const uint32_t koff = (uint32_t)((lane >> 4) * 16);

        for (int kt = 0; kt < KTEN; ++kt) {
            CP_WAIT(0);
            BAR_MMA();
            if (kt + 1 < KTEN) load_stage(sbase, kt + 1, gA, gB, tid);

            const int s = kt % STAGES;
            const uint32_t aTile = sbase + (uint32_t)(s * STAGE_BYTES);
            const uint32_t bTile = aTile + (uint32_t)(BM * RS);
            const uint32_t aAddr0 = aTile + (warp_m * 32 + lrow) * RS + koff;
            const uint32_t bAddr0 = bTile + (warp_n * 32 + lrow) * RS + koff;

#pragma unroll
            for (int kk = 0; kk < 4; ++kk) {
                const uint32_t kb = (uint32_t)(kk * 32);
                uint32_t a[2][4];
#pragma unroll
                for (int mi = 0; mi < 2; ++mi)
                    ldmatrix_x4(a[mi][0], a[mi][1], a[mi][2], a[mi][3],
                                aAddr0 + kb + (uint32_t)(mi * 16 * RS));
                uint32_t b[4][2];
#pragma unroll
                for (int p = 0; p < 2; ++p) {
                    uint32_t r0, r1, r2, r3;
                    ldmatrix_x4(r0, r1, r2, r3,
                                bAddr0 + kb + (uint32_t)(p * 16 * RS));
                    b[2 * p][0] = r0; b[2 * p + 1][0] = r1;
                    b[2 * p][1] = r2; b[2 * p + 1][1] = r3;
                }
#pragma unroll
                for (int mi = 0; mi < 2; ++mi)
#pragma unroll
                    for (int ni = 0; ni < 4; ++ni)
                        mma16832(acc[mi][ni], a[mi], b[ni]);
            }
        }
    } else {
        // ================= FMA warps: k in [768,1024) =================
        const int fw = wid - 16;                // 0..7 -> rows 16fw..16fw+15
#pragma unroll
        for (int i = 0; i < 16; ++i) { sacc[i][0] = 0u; sacc[i][1] = 0u; }

        const uint32_t bkBase = sbase + BK_OFF + (uint32_t)(4 * lane);
        const uint32_t ahBase = sbase + AH_OFF + (uint32_t)(fw * 16 * 512);

        for (int q = 0; q < 64; ++q) {          // 64 quads x 4 k
            const uint32_t k0 = (uint32_t)(q * 4);
            uint32_t bv0[4], bv1[4];
#pragma unroll
            for (int e = 0; e < 4; ++e) {
                bv0[e] = *reinterpret_cast<const uint32_t*>(
                    smem + (bkBase - sbase) + (k0 + e) * 272);
                bv1[e] = *reinterpret_cast<const uint32_t*>(
                    smem + (bkBase - sbase) + (k0 + e) * 272 + 128);
            }
#pragma unroll
            for (int i = 0; i < 16; ++i) {
                const uint2 av = *reinterpret_cast<const uint2*>(
                    smem + AH_OFF + (fw * 16 + i) * 512 + k0 * 2);
                const uint32_t d0 = __byte_perm(av.x, av.x, 0x1010);
                const uint32_t d1 = __byte_perm(av.x, av.x, 0x3232);
                const uint32_t d2 = __byte_perm(av.y, av.y, 0x1010);
                const uint32_t d3 = __byte_perm(av.y, av.y, 0x3232);
                sacc[i][0] = hfma2_acc(sacc[i][0], d0, bv0[0]);
                sacc[i][1] = hfma2_acc(sacc[i][1], d0, bv1[0]);
                sacc[i][0] = hfma2_acc(sacc[i][0], d1, bv0[1]);
                sacc[i][1] = hfma2_acc(sacc[i][1], d1, bv1[1]);
                sacc[i][0] = hfma2_acc(sacc[i][0], d2, bv0[2]);
                sacc[i][1] = hfma2_acc(sacc[i][1], d2, bv1[2]);
                sacc[i][0] = hfma2_acc(sacc[i][0], d3, bv0[3]);
                sacc[i][1] = hfma2_acc(sacc[i][1], d3, bv1[3]);
            }
        }
        (void)ahBase;
    }

    __syncthreads();   // barrier A: MMA done with stages; FMA done computing

    // FMA warps write partials into the (now dead) stage region as floats
    float* sc = reinterpret_cast<float*>(smem);
    if (wid >= 16) {
        const int fw = wid - 16;
#pragma unroll
        for (int i = 0; i < 16; ++i) {
            const int row = fw * 16 + i;
            const __half2 h0 = *reinterpret_cast<__half2*>(&sacc[i][0]);
            const __half2 h1 = *reinterpret_cast<__half2*>(&sacc[i][1]);
            const float2 f0 = __half22float2(h0);
            const float2 f1 = __half22float2(h1);
            *reinterpret_cast<float2*>(&sc[row * 128 + 2 * lane]) = f0;
            *reinterpret_cast<float2*>(&sc[row * 128 + 2 * lane + 64]) = f1;
        }
    }
    __syncthreads();   // barrier B: sc visible

    // ---------------- epilogue (MMA warps): exp + row/col sums ----------------
    if (wid < 16) {
        const int warp_m = wid & 3;
        const int warp_n = wid >> 2;
        const int m0 = i_base + warp_m * 32;
        const int n0 = j_base + warp_n * 32;
        const int gid = lane >> 2, tig = lane & 3;
        const int rl0 = warp_m * 32, cl0 = warp_n * 32;

        float rs[2][2] = {{0.f, 0.f}, {0.f, 0.f}};
        float cs[4][2];
#pragma unroll
        for (int ni = 0; ni < 4; ++ni) { cs[ni][0] = 0.f; cs[ni][1] = 0.f; }

#pragma unroll
        for (int mi = 0; mi < 2; ++mi)
#pragma unroll
            for (int ni = 0; ni < 4; ++ni) {
                const int r0 = rl0 + mi * 16 + gid;
                const int cc = cl0 + ni * 8 + 2 * tig;
                const float e0 = ex2f((acc[mi][ni][0] + sc[r0 * 128 + cc]) * K2LOG_S);
                const float e1 = ex2f((acc[mi][ni][1] + sc[r0 * 128 + cc + 1]) * K2LOG_S);
                const float e2 = ex2f((acc[mi][ni][2] + sc[(r0 + 8) * 128 + cc]) * K2LOG_S);
                const float e3 = ex2f((acc[mi][ni][3] + sc[(r0 + 8) * 128 + cc + 1]) * K2LOG_S);
                rs[mi][0] += e0 + e1;
                rs[mi][1] += e2 + e3;
                cs[ni][0] += e0 + e2;
                cs[ni][1] += e1 + e3;
            }

#pragma unroll
        for (int mi = 0; mi < 2; ++mi)
#pragma unroll
            for (int h = 0; h < 2; ++h) {
                float v = rs[mi][h];
                v += __shfl_xor_sync(0xffffffffu, v, 1);
                v += __shfl_xor_sync(0xffffffffu, v, 2);
                if (tig == 0)
                    atomicAdd(&g_rowsum[m0 + mi * 16 + h * 8 + gid], v);
            }
#pragma unroll
        for (int ni = 0; ni < 4; ++ni)
#pragma unroll
            for (int h = 0; h < 2; ++h) {
                float v = cs[ni][h];
                v += __shfl_xor_sync(0xffffffffu, v, 4);
                v += __shfl_xor_sync(0xffffffffu, v, 8);
                v += __shfl_xor_sync(0xffffffffu, v, 16);
                if (gid == 0)
                    atomicAdd(&g_colsum[n0 + ni * 8 + 2 * tig + h], v);
            }
    }
}

// ---------------------------------------------------------------------------
// Kernel 3: final log-reduce -> scalar loss
// ---------------------------------------------------------------------------
__global__ void __launch_bounds__(256) finalize_kernel(float* __restrict__ out) {
    const int tid = threadIdx.x;
    const double extra = (double)BROWS * 1e-6 + 1e-6;
    double acc = 0.0;
    for (int i = tid; i < BROWS; i += 256) {
        const double t = 2.0 * (double)g_diag[i] / 0.07;
        acc += t - log((double)g_rowsum[i] + extra) - log((double)g_colsum[i] + extra);
    }
    __shared__ double sb[256];
    sb[tid] = acc;
    __syncthreads();
#pragma unroll
    for (int s = 128; s; s >>= 1) {
        if (tid < s) sb[tid] += sb[tid + s];
        __syncthreads();
    }
    if (tid == 0) out[0] = (float)(sb[0] * (-1.0 / (2.0 * (double)BROWS)));
}

// ---------------------------------------------------------------------------
extern "C" void kernel_launch(void* const* d_in, const int* in_sizes, int n_in,
                              void* d_out, int out_size) {
    const float* x = (const float*)d_in[0];
    const float* y = (const float*)d_in[1];
    float* out = (float*)d_out;

    static int configured = 0;
    if (!configured) {
        cudaFuncSetAttribute(gemm_exp_kernel,
                             cudaFuncAttributeMaxDynamicSharedMemorySize, SMEM_BYTES);
        configured = 1;
    }

    norm_kernel<<<BROWS, 128>>>(x, y);
    gemm_exp_kernel<<<dim3(BROWS / BM, BROWS / BN), 768, SMEM_BYTES>>>();
    finalize_kernel<<<1, 256>>>(out);
}

// round 10
// speedup vs baseline: 1.6815x; 1.6333x over previous
#include <cuda_runtime.h>
#include <cuda_fp8.h>
#include <cstdint>

// ---------------------------------------------------------------------------
// Problem constants (fixed shapes: x,y = [4096,1024] fp32, scalar output)
// ---------------------------------------------------------------------------
#define BROWS 4096
#define DDIM  1024
#define EPSF  1e-6f

// fp8 quantization pre-scale (R3): e4m3 of 16*component; acc = 256*S.
// exp(S/tau) = exp2(acc * log2(e) / (0.07 * 256))
#define QSCALE 16.0f
#define K2LOG_S (20.6099287984152302f / 256.0f)

// GEMM: fp8 e4m3 mma.sync (proven pipe ceiling ~87 MAC/cyc/SMSP, R2-R9).
// R10: persistent CTAs (grid=148) with cross-tile cp.async prefetch — removes
// the 6 wave transitions (~8us) and per-tile pipeline refill (~3us) of R7.
#define BM 128
#define BN 128
#define BK 128
#define KT 8                    // chunks per tile
#define STAGES 4                // stage = chunk & 3 (8 % 4 == 0 keeps tiles aligned)
#define RS (BK + 16)            // smem row stride (pad -> conflict-free LDSM)
#define STAGE_BYTES ((BM + BN) * RS)             // 36864
#define SMEM_BYTES (STAGES * STAGE_BYTES)        // 147456
#define NSM 148
#define NTILES 1024             // (4096/128)^2

// ---------------------------------------------------------------------------
// Scratch (device globals: allocation-free rule)
// ---------------------------------------------------------------------------
__device__ uint8_t g_xq[(size_t)BROWS * DDIM];   // e4m3, row-major, K contiguous
__device__ uint8_t g_yq[(size_t)BROWS * DDIM];
__device__ float g_rowsum[BROWS];
__device__ float g_colsum[BROWS];
__device__ float g_diag[BROWS];

// ---------------------------------------------------------------------------
// PTX helpers (<= sm_89; nothing 'a'-gated)
// ---------------------------------------------------------------------------
static __device__ __forceinline__ uint32_t smem_u32(const void* p) {
    uint32_t a;
    asm("{ .reg .u64 t; cvta.to.shared.u64 t, %1; cvt.u32.u64 %0, t; }"
        : "=r"(a) : "l"(p));
    return a;
}
static __device__ __forceinline__ float ex2f(float x) {
    float y;
    asm("ex2.approx.ftz.f32 %0, %1;" : "=f"(y) : "f"(x));
    return y;
}
static __device__ __forceinline__ void cp16(uint32_t dst, const void* src) {
    asm volatile("cp.async.cg.shared.global [%0], [%1], 16;"
                 :: "r"(dst), "l"(src) : "memory");
}
#define CP_COMMIT() asm volatile("cp.async.commit_group;" ::: "memory")
#define CP_WAIT(n)  asm volatile("cp.async.wait_group %0;" :: "n"(n) : "memory")

static __device__ __forceinline__ void ldmatrix_x4(
    uint32_t& r0, uint32_t& r1, uint32_t& r2, uint32_t& r3, uint32_t addr) {
    asm volatile("ldmatrix.sync.aligned.m8n8.x4.shared.b16 {%0,%1,%2,%3}, [%4];"
                 : "=r"(r0), "=r"(r1), "=r"(r2), "=r"(r3) : "r"(addr));
}
static __device__ __forceinline__ void mma16832(
    float* d, const uint32_t* a, const uint32_t* b) {
    asm volatile(
        "mma.sync.aligned.m16n8k32.row.col.f32.e4m3.e4m3.f32 "
        "{%0,%1,%2,%3}, {%4,%5,%6,%7}, {%8,%9}, {%0,%1,%2,%3};"
        : "+f"(d[0]), "+f"(d[1]), "+f"(d[2]), "+f"(d[3])
        : "r"(a[0]), "r"(a[1]), "r"(a[2]), "r"(a[3]), "r"(b[0]), "r"(b[1]));
}
static __device__ __forceinline__ uint32_t pack_fp8x4(
    float a, float b, float c, float d) {
    const __nv_fp8x2_storage_t lo =
        __nv_cvt_float2_to_fp8x2(make_float2(a, b), __NV_SATFINITE, __NV_E4M3);
    const __nv_fp8x2_storage_t hi =
        __nv_cvt_float2_to_fp8x2(make_float2(c, d), __NV_SATFINITE, __NV_E4M3);
    return (uint32_t)lo | ((uint32_t)hi << 16);
}

// ---------------------------------------------------------------------------
// Kernel 1: block-per-row normalize -> e4m3 (scale 16), fp32 diag, zeroing
//   (exact R7 version: measured 9.8us)
// ---------------------------------------------------------------------------
__global__ void __launch_bounds__(128) norm_kernel(
    const float* __restrict__ x, const float* __restrict__ y) {
    const int i = blockIdx.x;
    const int tid = threadIdx.x;
    const int wid = tid >> 5, lane = tid & 31;

    const float4* xr = reinterpret_cast<const float4*>(x) + (size_t)i * 256;
    const float4* yr = reinterpret_cast<const float4*>(y) + (size_t)i * 256;
    const float4 x0 = xr[tid], x1 = xr[tid + 128];
    const float4 y0 = yr[tid], y1 = yr[tid + 128];

    float ssx = x0.x * x0.x + x0.y * x0.y + x0.z * x0.z + x0.w * x0.w
              + x1.x * x1.x + x1.y * x1.y + x1.z * x1.z + x1.w * x1.w;
    float ssy = y0.x * y0.x + y0.y * y0.y + y0.z * y0.z + y0.w * y0.w
              + y1.x * y1.x + y1.y * y1.y + y1.z * y1.z + y1.w * y1.w;
    float sxy = x0.x * y0.x + x0.y * y0.y + x0.z * y0.z + x0.w * y0.w
              + x1.x * y1.x + x1.y * y1.y + x1.z * y1.z + x1.w * y1.w;
#pragma unroll
    for (int m = 16; m; m >>= 1) {
        ssx += __shfl_xor_sync(0xffffffffu, ssx, m);
        ssy += __shfl_xor_sync(0xffffffffu, ssy, m);
        sxy += __shfl_xor_sync(0xffffffffu, sxy, m);
    }
    __shared__ float s0[4], s1[4], s2[4];
    if (lane == 0) { s0[wid] = ssx; s1[wid] = ssy; s2[wid] = sxy; }
    __syncthreads();
    const float a = s0[0] + s0[1] + s0[2] + s0[3];
    const float b = s1[0] + s1[1] + s1[2] + s1[3];
    const float c = s2[0] + s2[1] + s2[2] + s2[3];
    const float invx = 1.0f / fmaxf(sqrtf(a), EPSF);
    const float invy = 1.0f / fmaxf(sqrtf(b), EPSF);
    if (tid == 0) {
        g_diag[i] = c * invx * invy;
        g_rowsum[i] = 0.f;
        g_colsum[i] = 0.f;
    }
    const float qx = QSCALE * invx, qy = QSCALE * invy;
    uint32_t* ox = reinterpret_cast<uint32_t*>(g_xq + (size_t)i * DDIM);
    uint32_t* oy = reinterpret_cast<uint32_t*>(g_yq + (size_t)i * DDIM);
    ox[tid]       = pack_fp8x4(x0.x * qx, x0.y * qx, x0.z * qx, x0.w * qx);
    ox[tid + 128] = pack_fp8x4(x1.x * qx, x1.y * qx, x1.z * qx, x1.w * qx);
    oy[tid]       = pack_fp8x4(y0.x * qy, y0.y * qy, y0.z * qy, y0.w * qy);
    oy[tid + 128] = pack_fp8x4(y1.x * qy, y1.y * qy, y1.z * qy, y1.w * qy);
}

// ---------------------------------------------------------------------------
// Kernel 2: persistent fp8 GEMM + fused exp / row+col sums
//   grid = 148 CTAs; CTA b handles tiles b, b+148, ... with the cp.async
//   pipeline running continuously ACROSS tile boundaries.
// ---------------------------------------------------------------------------
static __device__ __forceinline__ void load_chunk(
    uint32_t sbase, int stage, int chunk,
    const uint8_t* gA, const uint8_t* gB, int tid) {
    const uint32_t aBase = sbase + (uint32_t)(stage * STAGE_BYTES);
    const uint32_t bBase = aBase + (uint32_t)(BM * RS);
#pragma unroll
    for (int r = 0; r < 2; ++r) {
        const int idx = tid + r * 512;
        const int row = idx >> 3, c = idx & 7;
        cp16(aBase + (uint32_t)(row * RS + c * 16),
             gA + (size_t)(chunk * BK) + (size_t)row * DDIM + c * 16);
        cp16(bBase + (uint32_t)(row * RS + c * 16),
             gB + (size_t)(chunk * BK) + (size_t)row * DDIM + c * 16);
    }
    CP_COMMIT();
}

__global__ void __launch_bounds__(512, 1) gemm_exp_kernel() {
    extern __shared__ uint8_t smem[];
    const uint32_t sbase = smem_u32(smem);
    const int tid = threadIdx.x;
    const int lane = tid & 31;
    const int wid = tid >> 5;
    const int warp_m = wid & 3;        // 0..3 -> 32-row slice
    const int warp_n = wid >> 2;       // 0..3 -> 32-col slice

    int t = blockIdx.x;
    const uint8_t* gA = g_xq + (size_t)((t & 31) * BM) * DDIM;
    const uint8_t* gB = g_yq + (size_t)((t >> 5) * BN) * DDIM;

    // prologue: stages 0..2 of the first tile
    load_chunk(sbase, 0, 0, gA, gB, tid);
    load_chunk(sbase, 1, 1, gA, gB, tid);
    load_chunk(sbase, 2, 2, gA, gB, tid);

    const uint32_t lrow = (uint32_t)(lane & 15);
    const uint32_t koff = (uint32_t)((lane >> 4) * 16);
    const int gid = lane >> 2, tig = lane & 3;

    while (true) {
        const int i_base = (t & 31) * BM;
        const int j_base = (t >> 5) * BN;
        const int nxt = t + NSM;
        const bool has_nxt = (nxt < NTILES);
        const uint8_t* gA2 = g_xq + (size_t)((nxt & 31) * BM) * DDIM;
        const uint8_t* gB2 = g_yq + (size_t)((nxt >> 5) * BN) * DDIM;

        float acc[2][4][4];
#pragma unroll
        for (int mi = 0; mi < 2; ++mi)
#pragma unroll
            for (int ni = 0; ni < 4; ++ni)
#pragma unroll
                for (int r = 0; r < 4; ++r) acc[mi][ni][r] = 0.f;

        for (int kt = 0; kt < KT; ++kt) {
            CP_WAIT(STAGES - 2);
            __syncthreads();
            // prefetch 3 chunks ahead; beyond this tile -> next tile's chunks
            const int p = kt + STAGES - 1;
            if (p < KT) {
                load_chunk(sbase, p & 3, p, gA, gB, tid);
            } else if (has_nxt) {
                load_chunk(sbase, p & 3, p - KT, gA2, gB2, tid);
            } else {
                CP_COMMIT();   // empty group keeps wait_group counts aligned
            }

            const uint32_t aTile = sbase + (uint32_t)((kt & 3) * STAGE_BYTES);
            const uint32_t bTile = aTile + (uint32_t)(BM * RS);
            const uint32_t aAddr0 = aTile + (warp_m * 32 + lrow) * RS + koff;
            const uint32_t bAddr0 = bTile + (warp_n * 32 + lrow) * RS + koff;

#pragma unroll
            for (int kk = 0; kk < 4; ++kk) {          // 4 x k32 = BK
                const uint32_t kb = (uint32_t)(kk * 32);
                uint32_t a[2][4];
#pragma unroll
                for (int mi = 0; mi < 2; ++mi)
                    ldmatrix_x4(a[mi][0], a[mi][1], a[mi][2], a[mi][3],
                                aAddr0 + kb + (uint32_t)(mi * 16 * RS));
                uint32_t b[4][2];
#pragma unroll
                for (int p2 = 0; p2 < 2; ++p2) {
                    uint32_t r0, r1, r2, r3;
                    ldmatrix_x4(r0, r1, r2, r3,
                                bAddr0 + kb + (uint32_t)(p2 * 16 * RS));
                    b[2 * p2][0] = r0; b[2 * p2 + 1][0] = r1;
                    b[2 * p2][1] = r2; b[2 * p2 + 1][1] = r3;
                }
#pragma unroll
                for (int mi = 0; mi < 2; ++mi)
#pragma unroll
                    for (int ni = 0; ni < 4; ++ni)
                        mma16832(acc[mi][ni], a[mi], b[ni]);
            }
        }

        // -------- fused epilogue: exp + row/col sums (overlaps prefetch) ----
        float rs[2][2] = {{0.f, 0.f}, {0.f, 0.f}};
        float cs[4][2];
#pragma unroll
        for (int ni = 0; ni < 4; ++ni) { cs[ni][0] = 0.f; cs[ni][1] = 0.f; }

#pragma unroll
        for (int mi = 0; mi < 2; ++mi)
#pragma unroll
            for (int ni = 0; ni < 4; ++ni) {
                const float e0 = ex2f(acc[mi][ni][0] * K2LOG_S);
                const float e1 = ex2f(acc[mi][ni][1] * K2LOG_S);
                const float e2 = ex2f(acc[mi][ni][2] * K2LOG_S);
                const float e3 = ex2f(acc[mi][ni][3] * K2LOG_S);
                rs[mi][0] += e0 + e1;
                rs[mi][1] += e2 + e3;
                cs[ni][0] += e0 + e2;
                cs[ni][1] += e1 + e3;
            }

        const int m0 = i_base + warp_m * 32;
        const int n0 = j_base + warp_n * 32;
#pragma unroll
        for (int mi = 0; mi < 2; ++mi)
#pragma unroll
            for (int h = 0; h < 2; ++h) {
                float v = rs[mi][h];
                v += __shfl_xor_sync(0xffffffffu, v, 1);
                v += __shfl_xor_sync(0xffffffffu, v, 2);
                if (tig == 0)
                    atomicAdd(&g_rowsum[m0 + mi * 16 + h * 8 + gid], v);
            }
#pragma unroll
        for (int ni = 0; ni < 4; ++ni)
#pragma unroll
            for (int h = 0; h < 2; ++h) {
                float v = cs[ni][h];
                v += __shfl_xor_sync(0xffffffffu, v, 4);
                v += __shfl_xor_sync(0xffffffffu, v, 8);
                v += __shfl_xor_sync(0xffffffffu, v, 16);
                if (gid == 0)
                    atomicAdd(&g_colsum[n0 + ni * 8 + 2 * tig + h], v);
            }

        if (!has_nxt) break;
        t = nxt;
        gA = gA2;
        gB = gB2;
    }
}

// ---------------------------------------------------------------------------
// Kernel 3: final log-reduce -> scalar loss
// ---------------------------------------------------------------------------
__global__ void __launch_bounds__(256) finalize_kernel(float* __restrict__ out) {
    const int tid = threadIdx.x;
    const double extra = (double)BROWS * 1e-6 + 1e-6;
    double acc = 0.0;
    for (int i = tid; i < BROWS; i += 256) {
        const double t = 2.0 * (double)g_diag[i] / 0.07;
        acc += t - log((double)g_rowsum[i] + extra) - log((double)g_colsum[i] + extra);
    }
    __shared__ double sb[256];
    sb[tid] = acc;
    __syncthreads();
#pragma unroll
    for (int s = 128; s; s >>= 1) {
        if (tid < s) sb[tid] += sb[tid + s];
        __syncthreads();
    }
    if (tid == 0) out[0] = (float)(sb[0] * (-1.0 / (2.0 * (double)BROWS)));
}

// ---------------------------------------------------------------------------
extern "C" void kernel_launch(void* const* d_in, const int* in_sizes, int n_in,
                              void* d_out, int out_size) {
    const float* x = (const float*)d_in[0];
    const float* y = (const float*)d_in[1];
    float* out = (float*)d_out;

    static int configured = 0;
    if (!configured) {
        cudaFuncSetAttribute(gemm_exp_kernel,
                             cudaFuncAttributeMaxDynamicSharedMemorySize, SMEM_BYTES);
        configured = 1;
    }

    norm_kernel<<<BROWS, 128>>>(x, y);
    gemm_exp_kernel<<<NSM, 512, SMEM_BYTES>>>();
    finalize_kernel<<<1, 256>>>(out);
}